// round 6
// baseline (speedup 1.0000x reference)
#include <cuda_runtime.h>
#include <math.h>

#define TPB 96          // 3 warps: warp0=Y, warp1/2=chroma; 1 thread = one 8x8 block
#define BSTRIDE 65      // block stride in floats -> conflict-free gather/scatter

typedef unsigned long long u64;

// ---- packed f32x2 primitives (sm_103a; ptxas never auto-fuses these) ----
__device__ __forceinline__ u64 pk2(float lo, float hi) {
    u64 r; asm("mov.b64 %0,{%1,%2};" : "=l"(r) : "f"(lo), "f"(hi)); return r;
}
__device__ __forceinline__ void up2(u64 v, float& a, float& b) {
    asm("mov.b64 {%0,%1},%2;" : "=f"(a), "=f"(b) : "l"(v));
}
__device__ __forceinline__ u64 add2(u64 a, u64 b) {
    u64 d; asm("add.rn.f32x2 %0,%1,%2;" : "=l"(d) : "l"(a), "l"(b)); return d;
}
__device__ __forceinline__ u64 mul2(u64 a, u64 b) {
    u64 d; asm("mul.rn.f32x2 %0,%1,%2;" : "=l"(d) : "l"(a), "l"(b)); return d;
}
__device__ __forceinline__ u64 fma2(u64 a, u64 b, u64 c) {
    u64 d; asm("fma.rn.f32x2 %0,%1,%2,%3;" : "=l"(d) : "l"(a), "l"(b), "l"(c)); return d;
}

// One 8-point DCT pass over 4 packed lanes: A[k][j] <- sum_i M[k][i]*A[i][j],
// using even/odd symmetry M[u][x] = +/- M[u][7-x]. Me/Mo are duplicated-pair
// coefficient tables in shared memory (uniform LDS.64 broadcasts).
__device__ __forceinline__ void f8(u64 A[8][4], const u64* __restrict__ Me,
                                   const u64* __restrict__ Mo, u64 NEG1)
{
    #pragma unroll
    for (int j = 0; j < 4; j++) {
        u64 s0 = add2(A[0][j], A[7][j]);
        u64 s1 = add2(A[1][j], A[6][j]);
        u64 s2 = add2(A[2][j], A[5][j]);
        u64 s3 = add2(A[3][j], A[4][j]);
        u64 d0 = fma2(A[7][j], NEG1, A[0][j]);   // exact a-b
        u64 d1 = fma2(A[6][j], NEG1, A[1][j]);
        u64 d2 = fma2(A[5][j], NEG1, A[2][j]);
        u64 d3 = fma2(A[4][j], NEG1, A[3][j]);
        #pragma unroll
        for (int k = 0; k < 4; k++) {
            u64 e = mul2(Me[k * 4 + 0], s0);
            e = fma2(Me[k * 4 + 1], s1, e);
            e = fma2(Me[k * 4 + 2], s2, e);
            e = fma2(Me[k * 4 + 3], s3, e);
            u64 o = mul2(Mo[k * 4 + 0], d0);
            o = fma2(Mo[k * 4 + 1], d1, o);
            o = fma2(Mo[k * 4 + 2], d2, o);
            o = fma2(Mo[k * 4 + 3], d3, o);
            A[2 * k][j]     = e;
            A[2 * k + 1][j] = o;
        }
    }
}

// Pair-register 8x8 transpose: switches row-packed <-> column-packed form.
// Pure register traffic (mov.b64 splits/joins), no shared memory.
__device__ __forceinline__ void tr8(u64 A[8][4])
{
    float f[8][8];
    #pragma unroll
    for (int i = 0; i < 8; i++)
        #pragma unroll
        for (int j = 0; j < 4; j++) up2(A[i][j], f[i][2 * j], f[i][2 * j + 1]);
    #pragma unroll
    for (int j = 0; j < 4; j++)
        #pragma unroll
        for (int k = 0; k < 4; k++) {
            A[2 * j][k]     = pk2(f[2 * k][2 * j],     f[2 * k + 1][2 * j]);
            A[2 * j + 1][k] = pk2(f[2 * k][2 * j + 1], f[2 * k + 1][2 * j + 1]);
        }
}

__global__ __launch_bounds__(TPB, 4)          // 4 CTAs/SM = 12 warps (was 3/9)
void jpeg_kernel(const float* __restrict__ img,
                 const float* __restrict__ r2y,
                 const float* __restrict__ y2r,
                 const float* __restrict__ C,
                 const float* __restrict__ ql,
                 const float* __restrict__ qc,
                 float* __restrict__ out,
                 int nbatch)
{
    __shared__ u64 sMe2[16];                 // duplicated-pair even coeffs M[2k][i], i=0..3
    __shared__ u64 sMo2[16];                 // duplicated-pair odd  coeffs M[2k+1][i]
    __shared__ u64 sQ2[2][32];               // packed (q[2i], q[2i+1]) pairs
    __shared__ u64 sQi2[2][32];              // packed reciprocal pairs
    __shared__ float sB[TPB * BSTRIDE];

    const int tid = threadIdx.x;

    // ---- table init: recover 1-D DCT basis from the 4-D coeff tensor ----
    if (tid < 32) {
        float a0 = ql[2 * tid], a1 = ql[2 * tid + 1];
        float b0 = qc[2 * tid], b1 = qc[2 * tid + 1];
        sQ2[0][tid]  = pk2(a0, a1);
        sQi2[0][tid] = pk2(1.0f / a0, 1.0f / a1);
        sQ2[1][tid]  = pk2(b0, b1);
        sQi2[1][tid] = pk2(1.0f / b0, 1.0f / b1);
        if (tid < 16) {
            const float m00 = sqrtf(C[0]);               // M[0][0]
            const int k = tid >> 2, i = tid & 3;
            float me = C[(2 * k) * 512 + i * 8] / m00;   // C[u,0,x,0] = M[u,x]*M[0,0]
            float mo = C[(2 * k + 1) * 512 + i * 8] / m00;
            sMe2[tid] = pk2(me, me);
            sMo2[tid] = pk2(mo, mo);
        }
    }

    const int gx0 = blockIdx.x << 6;    // 64-wide region
    const int gy0 = blockIdx.y << 5;    // 32-tall region
    const size_t plane = 512 * 512;
    const float* src = img + (size_t)blockIdx.z * 3 * plane;
    float*       dst = out + (size_t)blockIdx.z * 3 * plane;

    const float A00 = r2y[0], A01 = r2y[1], A02 = r2y[2];
    const float A10 = r2y[3], A11 = r2y[4], A12 = r2y[5];
    const float A20 = r2y[6], A21 = r2y[7], A22 = r2y[8];

    // ---- phase 1: load RGB (float4), convert to scaled YUV, scatter block-major ----
    #pragma unroll
    for (int it = 0; it < 6; it++) {
        int v = tid + it * TPB;
        if (v < 512) {                       // 512 float4 groups in a 32x64 region
            int ly = v >> 4;                 // 0..31
            int lx = (v & 15) << 2;          // 0..60 step 4 (stays inside one 8-block)
            size_t poff = (size_t)(gy0 + ly) * 512 + (gx0 + lx);
            float4 R4 = *(const float4*)(src + poff);
            float4 G4 = *(const float4*)(src + plane + poff);
            float4 B4 = *(const float4*)(src + 2 * plane + poff);
            int blk  = ((ly >> 3) << 3) + (lx >> 3);          // 0..31 within channel
            int soff = ((ly & 7) << 3) + (lx & 7);
            float rr[4] = {R4.x, R4.y, R4.z, R4.w};
            float gg[4] = {G4.x, G4.y, G4.z, G4.w};
            float bb[4] = {B4.x, B4.y, B4.z, B4.w};
            #pragma unroll
            for (int j = 0; j < 4; j++) {
                float Y = fmaf(A02, bb[j], fmaf(A01, gg[j], A00 * rr[j]));
                float U = fmaf(A12, bb[j], fmaf(A11, gg[j], A10 * rr[j]));
                float V = fmaf(A22, bb[j], fmaf(A21, gg[j], A20 * rr[j]));
                sB[(blk     ) * BSTRIDE + soff + j] = Y * 255.0f - 128.0f;
                sB[(blk + 32) * BSTRIDE + soff + j] = U * 255.0f - 128.0f;
                sB[(blk + 64) * BSTRIDE + soff + j] = V * 255.0f - 128.0f;
            }
        }
    }

    __syncthreads();

    // ---- phase 2: per-thread 8x8 (packed f32x2, even/odd fast DCT) ----
    {
        const int qi = (tid >= 32) ? 1 : 0;
        const u64 NEG1 = pk2(-1.0f, -1.0f);
        float* myB = &sB[tid * BSTRIDE];

        u64 A[8][4];
        // load + pack pairs of rows: A[x][rp] = (b[2rp][x], b[2rp+1][x])
        #pragma unroll
        for (int rp = 0; rp < 4; rp++)
            #pragma unroll
            for (int x = 0; x < 8; x++)
                A[x][rp] = pk2(myB[(2 * rp) * 8 + x], myB[(2 * rp + 1) * 8 + x]);

        f8(A, sMe2, sMo2, NEG1);     // forward row pass (SIMD over rows)
        tr8(A);                      // row-packed -> column-packed
        f8(A, sMe2, sMo2, NEG1);     // forward col pass (SIMD over cols)

        // quantize / dequantize, column-packed; round-half-even matches jnp.round
        #pragma unroll
        for (int v = 0; v < 8; v++)
            #pragma unroll
            for (int up = 0; up < 4; up++) {
                u64 t = mul2(A[v][up], sQi2[qi][v * 4 + up]);
                float x0, x1; up2(t, x0, x1);
                A[v][up] = mul2(pk2(rintf(x0), rintf(x1)), sQ2[qi][v * 4 + up]);
            }

        f8(A, sMe2, sMo2, NEG1);     // "inverse" col pass (reference reuses M)
        tr8(A);                      // column-packed -> row-packed
        f8(A, sMe2, sMo2, NEG1);     // "inverse" row pass

        // unpack + store
        #pragma unroll
        for (int wp = 0; wp < 4; wp++)
            #pragma unroll
            for (int y = 0; y < 8; y++) {
                float a, b; up2(A[y][wp], a, b);
                myB[(2 * wp) * 8 + y]     = a;
                myB[(2 * wp + 1) * 8 + y] = b;
            }
    }

    __syncthreads();

    // ---- phase 3: YUV' -> RGB, float4 stores ----
    const float D00 = y2r[0], D01 = y2r[1], D02 = y2r[2];
    const float D10 = y2r[3], D11 = y2r[4], D12 = y2r[5];
    const float D20 = y2r[6], D21 = y2r[7], D22 = y2r[8];
    const float inv255 = 1.0f / 255.0f;

    #pragma unroll
    for (int it = 0; it < 6; it++) {
        int v = tid + it * TPB;
        if (v < 512) {
            int ly = v >> 4;
            int lx = (v & 15) << 2;
            size_t poff = (size_t)(gy0 + ly) * 512 + (gx0 + lx);
            int blk  = ((ly >> 3) << 3) + (lx >> 3);
            int soff = ((ly & 7) << 3) + (lx & 7);
            float ro[4], go[4], bo[4];
            #pragma unroll
            for (int j = 0; j < 4; j++) {
                float Y = (sB[(blk     ) * BSTRIDE + soff + j] + 128.0f) * inv255;
                float U = (sB[(blk + 32) * BSTRIDE + soff + j] + 128.0f) * inv255;
                float V = (sB[(blk + 64) * BSTRIDE + soff + j] + 128.0f) * inv255;
                ro[j] = fmaf(D02, V, fmaf(D01, U, D00 * Y));
                go[j] = fmaf(D12, V, fmaf(D11, U, D10 * Y));
                bo[j] = fmaf(D22, V, fmaf(D21, U, D20 * Y));
            }
            *(float4*)(dst + poff)             = make_float4(ro[0], ro[1], ro[2], ro[3]);
            *(float4*)(dst + plane + poff)     = make_float4(go[0], go[1], go[2], go[3]);
            *(float4*)(dst + 2 * plane + poff) = make_float4(bo[0], bo[1], bo[2], bo[3]);
        }
    }
    (void)nbatch;
}

extern "C" void kernel_launch(void* const* d_in, const int* in_sizes, int n_in,
                              void* d_out, int out_size)
{
    const float* img = (const float*)d_in[0];
    const float* r2y = (const float*)d_in[1];
    const float* y2r = (const float*)d_in[2];
    const float* C   = (const float*)d_in[3];
    const float* ql  = (const float*)d_in[4];
    const float* qc  = (const float*)d_in[5];

    int nbatch = in_sizes[0] / (3 * 512 * 512);   // 16 for this problem
    dim3 grid(512 / 64, 512 / 32, nbatch);
    jpeg_kernel<<<grid, TPB>>>(img, r2y, y2r, C, ql, qc, (float*)d_out, nbatch);
}

// round 7
// speedup vs baseline: 1.1641x; 1.1641x over previous
#include <cuda_runtime.h>
#include <math.h>

#define TPB 96          // 3 warps: warp0=Y, warp1/2=chroma; 1 thread = one 8x8 block
#define BSTRIDE 66      // even stride: LDS.64/STS.64 conflict-free in phase 2

// 1-D orthonormal DCT-II coefficients: Kn = 0.5*cos(n*pi/16), K4 includes 1/sqrt(2)
#define K1 0.49039264020161522f
#define K2 0.46193976625564337f
#define K3 0.41573480615127262f
#define K4 0.35355339059327376f
#define K5 0.27778511650980111f
#define K6 0.19134171618254489f
#define K7 0.097545161008064134f

// JPEG quant tables (constants of the reference)
static __device__ constexpr float QLUM[64] = {
    16,11,10,16,24,40,51,61,  12,12,14,19,26,58,60,55,
    14,13,16,24,40,57,69,56,  14,17,22,29,51,87,80,62,
    18,22,37,56,68,109,103,77, 24,35,55,64,81,104,113,92,
    49,64,78,87,103,121,120,101, 72,92,95,98,112,100,103,99};
static __device__ constexpr float QCHR[64] = {
    17,18,24,47,99,99,99,99,  18,21,26,66,99,99,99,99,
    24,26,56,99,99,99,99,99,  47,66,99,99,99,99,99,99,
    99,99,99,99,99,99,99,99,  99,99,99,99,99,99,99,99,
    99,99,99,99,99,99,99,99,  99,99,99,99,99,99,99,99};

// 8-point DCT (stride S), even/odd symmetric: 8 FADD + 8 FMUL + 24 FFMA-imm.
// Same matrix applies for the reference's "inverse" (it re-contracts with M).
template<int S>
__device__ __forceinline__ void dct8(float* __restrict__ x)
{
    float s0 = x[0*S] + x[7*S], s1 = x[1*S] + x[6*S];
    float s2 = x[2*S] + x[5*S], s3 = x[3*S] + x[4*S];
    float d0 = x[0*S] - x[7*S], d1 = x[1*S] - x[6*S];
    float d2 = x[2*S] - x[5*S], d3 = x[3*S] - x[4*S];
    x[0*S] = fmaf( K4, s3, fmaf( K4, s2, fmaf( K4, s1, K4 * s0)));
    x[2*S] = fmaf(-K2, s3, fmaf(-K6, s2, fmaf( K6, s1, K2 * s0)));
    x[4*S] = fmaf( K4, s3, fmaf(-K4, s2, fmaf(-K4, s1, K4 * s0)));
    x[6*S] = fmaf(-K6, s3, fmaf( K2, s2, fmaf(-K2, s1, K6 * s0)));
    x[1*S] = fmaf( K7, d3, fmaf( K5, d2, fmaf( K3, d1, K1 * d0)));
    x[3*S] = fmaf(-K5, d3, fmaf(-K1, d2, fmaf(-K7, d1, K3 * d0)));
    x[5*S] = fmaf( K3, d3, fmaf( K7, d2, fmaf(-K1, d1, K5 * d0)));
    x[7*S] = fmaf(-K1, d3, fmaf( K3, d2, fmaf(-K5, d1, K7 * d0)));
}

__device__ __forceinline__ void quant64(float* __restrict__ B, const float* __restrict__ Q)
{
    #pragma unroll
    for (int j = 0; j < 64; j++)
        B[j] = rintf(B[j] * (1.0f / Q[j])) * Q[j];   // 1/Q folds to an immediate
}

__global__ __launch_bounds__(TPB, 5)
void jpeg_kernel(const float* __restrict__ img, float* __restrict__ out)
{
    __shared__ float sB[TPB * BSTRIDE];

    const int tid = threadIdx.x;
    const int gx0 = blockIdx.x << 6;    // 64-wide region
    const int gy0 = blockIdx.y << 5;    // 32-tall region
    const size_t plane = 512 * 512;
    const float* src = img + (size_t)blockIdx.z * 3 * plane;
    float*       dst = out + (size_t)blockIdx.z * 3 * plane;

    // ---- phase 1: load RGB (float4), RGB->YUV (hardcoded), *255-128, scatter block-major ----
    #pragma unroll
    for (int it = 0; it < 6; it++) {
        int v = tid + it * TPB;
        if (v < 512) {                       // 512 float4 groups in a 32x64 region
            int ly = v >> 4;                 // 0..31
            int lx = (v & 15) << 2;          // 0..60 step 4 (stays inside one 8-block)
            size_t poff = (size_t)(gy0 + ly) * 512 + (gx0 + lx);
            float4 R4 = *(const float4*)(src + poff);
            float4 G4 = *(const float4*)(src + plane + poff);
            float4 B4 = *(const float4*)(src + 2 * plane + poff);
            int base = (((ly >> 3) << 3) + (lx >> 3)) * BSTRIDE + ((ly & 7) << 3) + (lx & 7);
            float rr[4] = {R4.x, R4.y, R4.z, R4.w};
            float gg[4] = {G4.x, G4.y, G4.z, G4.w};
            float bb[4] = {B4.x, B4.y, B4.z, B4.w};
            float yv[4], uv[4], vv[4];
            #pragma unroll
            for (int j = 0; j < 4; j++) {
                float Y = fmaf(0.114f,  bb[j], fmaf(0.587f,   gg[j], 0.299f   * rr[j]));
                float U = fmaf(0.5f,    bb[j], fmaf(-0.3313f, gg[j], -0.1687f * rr[j]));
                float V = fmaf(-0.0813f,bb[j], fmaf(-0.4187f, gg[j], 0.5f     * rr[j]));
                yv[j] = fmaf(Y, 255.0f, -128.0f);
                uv[j] = fmaf(U, 255.0f, -128.0f);
                vv[j] = fmaf(V, 255.0f, -128.0f);
            }
            *(float2*)&sB[base]                        = make_float2(yv[0], yv[1]);
            *(float2*)&sB[base + 2]                    = make_float2(yv[2], yv[3]);
            *(float2*)&sB[base + 32 * BSTRIDE]         = make_float2(uv[0], uv[1]);
            *(float2*)&sB[base + 32 * BSTRIDE + 2]     = make_float2(uv[2], uv[3]);
            *(float2*)&sB[base + 64 * BSTRIDE]         = make_float2(vv[0], vv[1]);
            *(float2*)&sB[base + 64 * BSTRIDE + 2]     = make_float2(vv[2], vv[3]);
        }
    }

    __syncthreads();

    // ---- phase 2: per-thread 8x8, scalar immediates, all in registers ----
    {
        float* myB = &sB[tid * BSTRIDE];
        float B[64];
        #pragma unroll
        for (int i = 0; i < 32; i++) {       // LDS.64, conflict-free (stride 66)
            float2 t = *(const float2*)(&myB[2 * i]);
            B[2 * i] = t.x;  B[2 * i + 1] = t.y;
        }

        #pragma unroll
        for (int r = 0; r < 8; r++) dct8<1>(&B[r * 8]);   // rows (contract over y -> v)
        #pragma unroll
        for (int c = 0; c < 8; c++) dct8<8>(&B[c]);       // cols (contract over x -> u)

        if (tid < 32) quant64(B, QLUM);       // warp-uniform branch: warp0 = Y
        else          quant64(B, QCHR);       // warps 1,2 = chroma

        #pragma unroll
        for (int c = 0; c < 8; c++) dct8<8>(&B[c]);       // reference "inverse" reuses M
        #pragma unroll
        for (int r = 0; r < 8; r++) dct8<1>(&B[r * 8]);

        #pragma unroll
        for (int i = 0; i < 32; i++)
            *(float2*)(&myB[2 * i]) = make_float2(B[2 * i], B[2 * i + 1]);
    }

    __syncthreads();

    // ---- phase 3: +128, /255, YUV->RGB (hardcoded), float4 stores ----
    const float inv255 = 1.0f / 255.0f;
    #pragma unroll
    for (int it = 0; it < 6; it++) {
        int v = tid + it * TPB;
        if (v < 512) {
            int ly = v >> 4;
            int lx = (v & 15) << 2;
            size_t poff = (size_t)(gy0 + ly) * 512 + (gx0 + lx);
            int base = (((ly >> 3) << 3) + (lx >> 3)) * BSTRIDE + ((ly & 7) << 3) + (lx & 7);
            float2 y01 = *(const float2*)&sB[base];
            float2 y23 = *(const float2*)&sB[base + 2];
            float2 u01 = *(const float2*)&sB[base + 32 * BSTRIDE];
            float2 u23 = *(const float2*)&sB[base + 32 * BSTRIDE + 2];
            float2 v01 = *(const float2*)&sB[base + 64 * BSTRIDE];
            float2 v23 = *(const float2*)&sB[base + 64 * BSTRIDE + 2];
            float yy[4] = {y01.x, y01.y, y23.x, y23.y};
            float uu[4] = {u01.x, u01.y, u23.x, u23.y};
            float vv[4] = {v01.x, v01.y, v23.x, v23.y};
            float ro[4], go[4], bo[4];
            #pragma unroll
            for (int j = 0; j < 4; j++) {
                float Y = (yy[j] + 128.0f) * inv255;
                float U = (uu[j] + 128.0f) * inv255;
                float V = (vv[j] + 128.0f) * inv255;
                ro[j] = fmaf(1.402f, V, Y);
                go[j] = fmaf(-0.71414f, V, fmaf(-0.34414f, U, Y));
                bo[j] = fmaf(1.772f, U, Y);
            }
            *(float4*)(dst + poff)             = make_float4(ro[0], ro[1], ro[2], ro[3]);
            *(float4*)(dst + plane + poff)     = make_float4(go[0], go[1], go[2], go[3]);
            *(float4*)(dst + 2 * plane + poff) = make_float4(bo[0], bo[1], bo[2], bo[3]);
        }
    }
}

extern "C" void kernel_launch(void* const* d_in, const int* in_sizes, int n_in,
                              void* d_out, int out_size)
{
    const float* img = (const float*)d_in[0];
    int nbatch = in_sizes[0] / (3 * 512 * 512);   // 16 for this problem
    dim3 grid(512 / 64, 512 / 32, nbatch);
    jpeg_kernel<<<grid, TPB>>>(img, (float*)d_out);
}

// round 10
// speedup vs baseline: 1.2465x; 1.0708x over previous
#include <cuda_runtime.h>
#include <math.h>

#define TPB 96          // 3 warps: warp0=Y, warp1/2=chroma; 1 thread = one 8x8 block
#define BSTRIDE 68      // multiple of 4: LDS.128/STS.128, conflict-free in phase 2
#define RMAGIC 12582912.0f   // 1.5*2^23: (x+M)-M = round-half-even(x) for |x|<2^22

// 1-D orthonormal DCT-II coefficients: Kn = 0.5*cos(n*pi/16), K4 includes 1/sqrt(2)
#define K1 0.49039264020161522f
#define K2 0.46193976625564337f
#define K3 0.41573480615127262f
#define K4 0.35355339059327376f
#define K5 0.27778511650980111f
#define K6 0.19134171618254489f
#define K7 0.097545161008064134f

// JPEG quant tables (constants of the reference)
static __device__ constexpr float QLUM[64] = {
    16,11,10,16,24,40,51,61,  12,12,14,19,26,58,60,55,
    14,13,16,24,40,57,69,56,  14,17,22,29,51,87,80,62,
    18,22,37,56,68,109,103,77, 24,35,55,64,81,104,113,92,
    49,64,78,87,103,121,120,101, 72,92,95,98,112,100,103,99};
static __device__ constexpr float QCHR[64] = {
    17,18,24,47,99,99,99,99,  18,21,26,66,99,99,99,99,
    24,26,56,99,99,99,99,99,  47,66,99,99,99,99,99,99,
    99,99,99,99,99,99,99,99,  99,99,99,99,99,99,99,99,
    99,99,99,99,99,99,99,99,  99,99,99,99,99,99,99,99};

// 8-point DCT (stride S), even/odd symmetric: 8 FADD + 8 FMUL + 24 FFMA-imm.
// Same matrix applies for the reference's "inverse" (it re-contracts with M).
template<int S>
__device__ __forceinline__ void dct8(float* __restrict__ x)
{
    float s0 = x[0*S] + x[7*S], s1 = x[1*S] + x[6*S];
    float s2 = x[2*S] + x[5*S], s3 = x[3*S] + x[4*S];
    float d0 = x[0*S] - x[7*S], d1 = x[1*S] - x[6*S];
    float d2 = x[2*S] - x[5*S], d3 = x[3*S] - x[4*S];
    x[0*S] = fmaf( K4, s3, fmaf( K4, s2, fmaf( K4, s1, K4 * s0)));
    x[2*S] = fmaf(-K2, s3, fmaf(-K6, s2, fmaf( K6, s1, K2 * s0)));
    x[4*S] = fmaf( K4, s3, fmaf(-K4, s2, fmaf(-K4, s1, K4 * s0)));
    x[6*S] = fmaf(-K6, s3, fmaf( K2, s2, fmaf(-K2, s1, K6 * s0)));
    x[1*S] = fmaf( K7, d3, fmaf( K5, d2, fmaf( K3, d1, K1 * d0)));
    x[3*S] = fmaf(-K5, d3, fmaf(-K1, d2, fmaf(-K7, d1, K3 * d0)));
    x[5*S] = fmaf( K3, d3, fmaf( K7, d2, fmaf(-K1, d1, K5 * d0)));
    x[7*S] = fmaf(-K1, d3, fmaf( K3, d2, fmaf(-K5, d1, K7 * d0)));
}

// quant/dequant via magic-constant round-half-even: all fast-pipe imm ops, no FRND
__device__ __forceinline__ void quant64(float* __restrict__ B, const float* __restrict__ Q)
{
    #pragma unroll
    for (int j = 0; j < 64; j++) {
        float t = fmaf(B[j], 1.0f / Q[j], RMAGIC);   // 1/Q folds to an immediate
        B[j] = (t - RMAGIC) * Q[j];
    }
}

__global__ __launch_bounds__(TPB, 6)          // reg target 112 -> 6 CTAs = 18 warps/SM
void jpeg_kernel(const float* __restrict__ img, float* __restrict__ out)
{
    __shared__ float sB[TPB * BSTRIDE];

    const int tid = threadIdx.x;
    const int gx0 = blockIdx.x << 6;    // 64-wide region
    const int gy0 = blockIdx.y << 5;    // 32-tall region
    const size_t plane = 512 * 512;
    const float* src = img + (size_t)blockIdx.z * 3 * plane;
    float*       dst = out + (size_t)blockIdx.z * 3 * plane;

    // ---- phase 1: load RGB (float4), RGB->YUV (hardcoded), *255-128, scatter block-major ----
    #pragma unroll
    for (int it = 0; it < 6; it++) {
        int v = tid + it * TPB;
        if (v < 512) {                       // 512 float4 groups in a 32x64 region
            int ly = v >> 4;                 // 0..31
            int lx = (v & 15) << 2;          // 0..60 step 4 (stays inside one 8-block)
            size_t poff = (size_t)(gy0 + ly) * 512 + (gx0 + lx);
            float4 R4 = *(const float4*)(src + poff);
            float4 G4 = *(const float4*)(src + plane + poff);
            float4 B4 = *(const float4*)(src + 2 * plane + poff);
            int base = (((ly >> 3) << 3) + (lx >> 3)) * BSTRIDE + ((ly & 7) << 3) + (lx & 7);
            float rr[4] = {R4.x, R4.y, R4.z, R4.w};
            float gg[4] = {G4.x, G4.y, G4.z, G4.w};
            float bb[4] = {B4.x, B4.y, B4.z, B4.w};
            float yv[4], uv[4], vv[4];
            #pragma unroll
            for (int j = 0; j < 4; j++) {
                float Y = fmaf(0.114f,  bb[j], fmaf(0.587f,   gg[j], 0.299f   * rr[j]));
                float U = fmaf(0.5f,    bb[j], fmaf(-0.3313f, gg[j], -0.1687f * rr[j]));
                float V = fmaf(-0.0813f,bb[j], fmaf(-0.4187f, gg[j], 0.5f     * rr[j]));
                yv[j] = fmaf(Y, 255.0f, -128.0f);
                uv[j] = fmaf(U, 255.0f, -128.0f);
                vv[j] = fmaf(V, 255.0f, -128.0f);
            }
            *(float4*)&sB[base]                = make_float4(yv[0], yv[1], yv[2], yv[3]);
            *(float4*)&sB[base + 32 * BSTRIDE] = make_float4(uv[0], uv[1], uv[2], uv[3]);
            *(float4*)&sB[base + 64 * BSTRIDE] = make_float4(vv[0], vv[1], vv[2], vv[3]);
        }
    }

    __syncthreads();

    // ---- phase 2: per-thread 8x8, scalar immediates, all in registers ----
    {
        float* myB = &sB[tid * BSTRIDE];
        float B[64];
        #pragma unroll
        for (int i = 0; i < 16; i++) {       // LDS.128, conflict-free (stride 68)
            float4 t = *(const float4*)(&myB[4 * i]);
            B[4*i] = t.x;  B[4*i+1] = t.y;  B[4*i+2] = t.z;  B[4*i+3] = t.w;
        }

        #pragma unroll
        for (int r = 0; r < 8; r++) dct8<1>(&B[r * 8]);   // rows (contract over y -> v)
        #pragma unroll
        for (int c = 0; c < 8; c++) dct8<8>(&B[c]);       // cols (contract over x -> u)

        if (tid < 32) quant64(B, QLUM);       // warp-uniform branch: warp0 = Y
        else          quant64(B, QCHR);       // warps 1,2 = chroma

        #pragma unroll
        for (int c = 0; c < 8; c++) dct8<8>(&B[c]);       // reference "inverse" reuses M
        #pragma unroll
        for (int r = 0; r < 8; r++) dct8<1>(&B[r * 8]);

        #pragma unroll
        for (int i = 0; i < 16; i++)
            *(float4*)(&myB[4 * i]) = make_float4(B[4*i], B[4*i+1], B[4*i+2], B[4*i+3]);
    }

    __syncthreads();

    // ---- phase 3: +128, /255, YUV->RGB (hardcoded), float4 stores ----
    const float inv255 = 1.0f / 255.0f;
    #pragma unroll
    for (int it = 0; it < 6; it++) {
        int v = tid + it * TPB;
        if (v < 512) {
            int ly = v >> 4;
            int lx = (v & 15) << 2;
            size_t poff = (size_t)(gy0 + ly) * 512 + (gx0 + lx);
            int base = (((ly >> 3) << 3) + (lx >> 3)) * BSTRIDE + ((ly & 7) << 3) + (lx & 7);
            float4 y4 = *(const float4*)&sB[base];
            float4 u4 = *(const float4*)&sB[base + 32 * BSTRIDE];
            float4 v4 = *(const float4*)&sB[base + 64 * BSTRIDE];
            float yy[4] = {y4.x, y4.y, y4.z, y4.w};
            float uu[4] = {u4.x, u4.y, u4.z, u4.w};
            float vv[4] = {v4.x, v4.y, v4.z, v4.w};
            float ro[4], go[4], bo[4];
            #pragma unroll
            for (int j = 0; j < 4; j++) {
                float Y = (yy[j] + 128.0f) * inv255;
                float U = (uu[j] + 128.0f) * inv255;
                float V = (vv[j] + 128.0f) * inv255;
                ro[j] = fmaf(1.402f, V, Y);
                go[j] = fmaf(-0.71414f, V, fmaf(-0.34414f, U, Y));
                bo[j] = fmaf(1.772f, U, Y);
            }
            *(float4*)(dst + poff)             = make_float4(ro[0], ro[1], ro[2], ro[3]);
            *(float4*)(dst + plane + poff)     = make_float4(go[0], go[1], go[2], go[3]);
            *(float4*)(dst + 2 * plane + poff) = make_float4(bo[0], bo[1], bo[2], bo[3]);
        }
    }
}

extern "C" void kernel_launch(void* const* d_in, const int* in_sizes, int n_in,
                              void* d_out, int out_size)
{
    const float* img = (const float*)d_in[0];
    int nbatch = in_sizes[0] / (3 * 512 * 512);   // 16 for this problem
    dim3 grid(512 / 64, 512 / 32, nbatch);
    jpeg_kernel<<<grid, TPB>>>(img, (float*)d_out);
}